// round 6
// baseline (speedup 1.0000x reference)
#include <cuda_runtime.h>
#include <math.h>

#define NBATCH  16
#define NATOM   512
#define NEIGH   64
#define NPAIR   (NATOM*NEIGH)        /* 32768  */
#define TOTATOM (NBATCH*NATOM)       /* 8192   */
#define NPTOT   (NBATCH*NPAIR)       /* 524288 */
#define NWAVE   8
#define NL      13
#define NFEAT   104                  /* NL * NWAVE */
#define NORBIT  128
#define GATOMS  16

#define PBLK    32                   /* k_pairs blocks per batch            */
#define PPB     1024                 /* pairs per k_pairs block             */
#define SLOT    16                   /* sub-bucket slots per (block, atom)  */
#define RCAP    512                  /* max records per atom (32*16)        */

// d_rec[((b*PBLK + blk)*NATOM + atom_local)*SLOT + pos] : (dx,dy,dz,species)
__device__ float4 d_rec[(size_t)NBATCH * PBLK * NATOM * SLOT];
// d_cnt[(b*PBLK + blk)*NATOM + atom_local] : written wholesale each run
__device__ int    d_cnt[NBATCH * PBLK * NATOM];
__device__ float  d_sw[(size_t)TOTATOM * NFEAT];

// ---------------------------------------------------------------------------
// Kernel 1: displacement + species, binned via SMEM cursors (no global RMW).
// ---------------------------------------------------------------------------
__global__ void __launch_bounds__(256)
k_pairs(const float* __restrict__ cart,
        const int*   __restrict__ species,
        const int*   __restrict__ atom_index,
        const float* __restrict__ shifts)
{
    __shared__ float scart[NATOM * 3];
    __shared__ int   ssp  [NATOM];
    __shared__ int   scur [NATOM];

    const int blk = blockIdx.x;               // 0..31 within batch
    const int b   = blockIdx.y;
    const int tid = threadIdx.x;

    const float* cb = cart + (size_t)b * NATOM * 3;
    for (int i = tid; i < NATOM * 3; i += 256) scart[i] = cb[i];
    for (int i = tid; i < NATOM;     i += 256) {
        ssp[i]  = species[b * NATOM + i];
        scur[i] = 0;
    }
    __syncthreads();

    const size_t base = ((size_t)(b * PBLK + blk)) * NATOM;

#pragma unroll
    for (int u = 0; u < 4; ++u) {
        const int p_loc = blk * PPB + u * 256 + tid;
        const int p     = b * NPAIR + p_loc;

        const int i_loc = atom_index[p];
        const int j_loc = atom_index[NPTOT + p];

        float dx = scart[3*i_loc+0] - scart[3*j_loc+0] + shifts[3*p+0];
        float dy = scart[3*i_loc+1] - scart[3*j_loc+1] + shifts[3*p+1];
        float dz = scart[3*i_loc+2] - scart[3*j_loc+2] + shifts[3*p+2];

        int pos = atomicAdd(&scur[i_loc], 1);     // SMEM atomic (~30 cyc)
        if (pos < SLOT)
            d_rec[(base + i_loc) * SLOT + pos] =
                make_float4(dx, dy, dz, __int_as_float(ssp[j_loc]));
    }
    __syncthreads();

    for (int i = tid; i < NATOM; i += 256) {      // coalesced count flush
        int c = scur[i];
        d_cnt[base + i] = c < SLOT ? c : SLOT;
    }
}

// ---------------------------------------------------------------------------
// Kernel 2a: block per atom -> sw[13][8].
// Gather 32 sub-buckets (warp-scanned offsets), then phases A/B + shuffle red.
// ---------------------------------------------------------------------------
__global__ void __launch_bounds__(128)
k_accum(const float* __restrict__ rs,
        const float* __restrict__ inta,
        const float* __restrict__ params,
        const float* __restrict__ cutoff,
        float*       __restrict__ swout)
{
    __shared__ float4 recs[RCAP];
    __shared__ float2 dfc [RCAP];
    __shared__ float  stab[96];       // [0:32) rs, [32:64) inta, [64:96) params
    __shared__ float  red [NL * NWAVE * 4];
    __shared__ int    scnt[32], soff[32], stot;

    const int atom = blockIdx.x;
    const int aloc = atom & (NATOM - 1);
    const int b    = atom >> 9;
    const int t    = threadIdx.x;
    const int warp = t >> 5;
    const int lane = t & 31;

    if (t < 32) {
        stab[t]      = rs[t];
        stab[32 + t] = inta[t];
        stab[64 + t] = params[t];
        int c = d_cnt[(b * PBLK + t) * NATOM + aloc];
        scnt[t] = c;
        int x = c;
#pragma unroll
        for (int dd = 1; dd < 32; dd <<= 1) {
            int y = __shfl_up_sync(0xffffffffu, x, dd);
            if (lane >= dd) x += y;
        }
        soff[t] = x - c;
        if (t == 31) stot = x;
    }
    __syncthreads();

    const int n = stot;
    // copy runs: warp w handles sub-buckets w, w+4, ..., lanes = slot index
    for (int r = warp; r < PBLK; r += 4) {
        int c = scnt[r];
        if (lane < c)
            recs[soff[r] + lane] =
                d_rec[((size_t)(b * PBLK + r) * NATOM + aloc) * SLOT + lane];
    }
    __syncthreads();

    // Phase A: per-pair distance + cutoff
    const float icp = 3.14159265358979323846f / cutoff[0];
    for (int p = t; p < n; p += 128) {
        float4 v = recs[p];
        float d  = sqrtf(v.x*v.x + v.y*v.y + v.z*v.z);
        float c  = 0.5f * __cosf(d * icp) + 0.5f;
        dfc[p]   = make_float2(d, c * c);
    }
    __syncthreads();

    // Phase B: thread = (w = t&7, slice = t>>3)
    const int w  = t & 7;
    const int sl = t >> 3;

    float acc[NL];
#pragma unroll
    for (int l = 0; l < NL; ++l) acc[l] = 0.f;

    for (int p = sl; p < n; p += 16) {
        float4 v  = recs[p];
        float2 df = dfc[p];
        int   sp  = __float_as_int(v.w);
        float tt  = df.x - stab[sp*8 + w];
        float r   = stab[64 + sp*8 + w] * __expf(stab[32 + sp*8 + w] * tt * tt);
        float q   = df.y * r;
        float qx = q * v.x, qy = q * v.y, qz = q * v.z;
        acc[0]  += q;
        acc[1]  += qx;        acc[2]  += qy;        acc[3]  += qz;
        acc[4]  += qx * v.x;  acc[5]  += qx * v.y;  acc[6]  += qx * v.z;
        acc[7]  += qy * v.x;  acc[8]  += qy * v.y;  acc[9]  += qy * v.z;
        acc[10] += qz * v.x;  acc[11] += qz * v.y;  acc[12] += qz * v.z;
    }

#pragma unroll
    for (int l = 0; l < NL; ++l) {
        acc[l] += __shfl_xor_sync(0xffffffffu, acc[l], 8);
        acc[l] += __shfl_xor_sync(0xffffffffu, acc[l], 16);
    }
    if (lane < 8) {
#pragma unroll
        for (int l = 0; l < NL; ++l)
            red[(l * NWAVE + lane) * 4 + warp] = acc[l];
    }
    __syncthreads();

    if (t < NFEAT) {
        float4 v = *reinterpret_cast<const float4*>(&red[t * 4]);
        swout[(size_t)atom * NFEAT + t] = (v.x + v.y) + (v.z + v.w);
    }
}

// ---------------------------------------------------------------------------
// Kernel 2b: density[atom][m] = sum_l ( sum_w sw[l][w]*hp[l][w][m] )^2
// ---------------------------------------------------------------------------
__global__ void __launch_bounds__(128)
k_stage2(const float* __restrict__ hyper,      // (3, 8, 128)
         const int*   __restrict__ index_para, // (13,)
         const float* __restrict__ sw,         // (8192, 104)
         float*       __restrict__ out)        // (8192, 128)
{
    const int t = threadIdx.x;

    float hp[NFEAT];
#pragma unroll
    for (int l = 0; l < NL; ++l) {
        int ip = index_para[l];
#pragma unroll
        for (int w = 0; w < NWAVE; ++w)
            hp[l*NWAVE + w] = hyper[(ip*NWAVE + w)*NORBIT + t];
    }

    __shared__ float swsm[GATOMS * NFEAT];
    const int base = blockIdx.x * GATOMS;

    for (int i = t; i < GATOMS * NFEAT; i += 128)
        swsm[i] = sw[(size_t)base * NFEAT + i];
    __syncthreads();

#pragma unroll 2
    for (int g = 0; g < GATOMS; ++g) {
        const float4* s4 = reinterpret_cast<const float4*>(&swsm[g * NFEAT]);
        float dens = 0.f;
#pragma unroll
        for (int l = 0; l < NL; ++l) {
            float4 a = s4[l*2], bb = s4[l*2+1];
            float h = a.x*hp[l*8+0] + a.y*hp[l*8+1] + a.z*hp[l*8+2] + a.w*hp[l*8+3]
                    + bb.x*hp[l*8+4] + bb.y*hp[l*8+5] + bb.z*hp[l*8+6] + bb.w*hp[l*8+7];
            dens += h * h;
        }
        out[(size_t)(base + g)*NORBIT + t] = dens;
    }
}

// ---------------------------------------------------------------------------
extern "C" void kernel_launch(void* const* d_in, const int* in_sizes, int n_in,
                              void* d_out, int out_size)
{
    const float* cart    = (const float*)d_in[0];
    const int*   species = (const int*)  d_in[2];
    const int*   aidx    = (const int*)  d_in[3];
    const float* shifts  = (const float*)d_in[4];
    const float* rs      = (const float*)d_in[5];
    const float* inta    = (const float*)d_in[6];
    const float* params  = (const float*)d_in[7];
    const float* hyper   = (const float*)d_in[8];
    const int*   ipara   = (const int*)  d_in[9];
    const float* cutoff  = (const float*)d_in[10];
    float*       out     = (float*)d_out;

    void* swp = nullptr;
    cudaGetSymbolAddress(&swp, d_sw);

    dim3 pgrid(PBLK, NBATCH);
    k_pairs<<<pgrid, 256>>>(cart, species, aidx, shifts);
    k_accum<<<TOTATOM, 128>>>(rs, inta, params, cutoff, (float*)swp);
    k_stage2<<<TOTATOM / GATOMS, 128>>>(hyper, ipara, (const float*)swp, out);
}

// round 7
// speedup vs baseline: 1.1915x; 1.1915x over previous
#include <cuda_runtime.h>
#include <math.h>

#define NBATCH  16
#define NATOM   512
#define NEIGH   64
#define NPAIR   (NATOM*NEIGH)        /* 32768  */
#define TOTATOM (NBATCH*NATOM)       /* 8192   */
#define NPTOT   (NBATCH*NPAIR)       /* 524288 */
#define NWAVE   8
#define NL      13
#define NFEAT   104                  /* NL * NWAVE */
#define NORBIT  128
#define GATOMS  16

#define PBLK    32                   /* k_pairs blocks per batch            */
#define PPB     1024                 /* pairs per k_pairs block             */
#define SLOT    16                   /* slots per (atom, block) cell        */
#define RCAP    512                  /* SMEM record capacity per atom       */

// Transposed scratch: one atom's 32 cells are contiguous (8 KB window).
// d_rec[((b*NATOM + atom)*PBLK + blk)*SLOT + slot] : (dx,dy,dz,species)
__device__ float4 d_rec[(size_t)TOTATOM * PBLK * SLOT];
// d_cnt[(b*NATOM + atom)*PBLK + blk] : written wholesale each run
__device__ int    d_cnt[TOTATOM * PBLK];
__device__ float  d_sw[(size_t)TOTATOM * NFEAT];

// ---------------------------------------------------------------------------
// Kernel 1: displacement + species, binned via SMEM cursors (no global RMW).
// ---------------------------------------------------------------------------
__global__ void __launch_bounds__(256)
k_pairs(const float* __restrict__ cart,
        const int*   __restrict__ species,
        const int*   __restrict__ atom_index,
        const float* __restrict__ shifts)
{
    __shared__ float scart[NATOM * 3];
    __shared__ int   ssp  [NATOM];
    __shared__ int   scur [NATOM];

    const int blk = blockIdx.x;               // 0..31 within batch
    const int b   = blockIdx.y;
    const int tid = threadIdx.x;

    const float* cb = cart + (size_t)b * NATOM * 3;
    for (int i = tid; i < NATOM * 3; i += 256) scart[i] = cb[i];
    for (int i = tid; i < NATOM;     i += 256) {
        ssp[i]  = species[b * NATOM + i];
        scur[i] = 0;
    }
    __syncthreads();

#pragma unroll
    for (int u = 0; u < 4; ++u) {
        const int p_loc = blk * PPB + u * 256 + tid;
        const int p     = b * NPAIR + p_loc;

        const int i_loc = atom_index[p];
        const int j_loc = atom_index[NPTOT + p];

        float dx = scart[3*i_loc+0] - scart[3*j_loc+0] + shifts[3*p+0];
        float dy = scart[3*i_loc+1] - scart[3*j_loc+1] + shifts[3*p+1];
        float dz = scart[3*i_loc+2] - scart[3*j_loc+2] + shifts[3*p+2];

        int pos = atomicAdd(&scur[i_loc], 1);     // SMEM atomic
        if (pos < SLOT)
            d_rec[(((size_t)(b * NATOM + i_loc)) * PBLK + blk) * SLOT + pos] =
                make_float4(dx, dy, dz, __int_as_float(ssp[j_loc]));
    }
    __syncthreads();

    for (int i = tid; i < NATOM; i += 256) {
        int c = scur[i];
        d_cnt[(b * NATOM + i) * PBLK + blk] = c < SLOT ? c : SLOT;
    }
}

// ---------------------------------------------------------------------------
// Kernel 2a: block per atom -> sw[13][8].
// Contiguous per-atom gather: counts = 1 sector; slots 0-3 of every cell in
// one parallel pass; rare c>4 remainder serial. Then phases A/B + shuffle red.
// ---------------------------------------------------------------------------
__global__ void __launch_bounds__(128)
k_accum(const float* __restrict__ rs,
        const float* __restrict__ inta,
        const float* __restrict__ params,
        const float* __restrict__ cutoff,
        float*       __restrict__ swout)
{
    __shared__ float4 recs[RCAP];
    __shared__ float2 dfc [RCAP];
    __shared__ float  stab[96];       // [0:32) rs, [32:64) inta, [64:96) params
    __shared__ float  red [NL * NWAVE * 4];
    __shared__ int    scnt[32], soff[32], stot;

    const int atom = blockIdx.x;      // global atom id = b*NATOM + aloc
    const int t    = threadIdx.x;
    const int warp = t >> 5;
    const int lane = t & 31;

    const float4* src = &d_rec[(size_t)atom * PBLK * SLOT];

    if (t < 32) {
        stab[t]      = rs[t];
        stab[32 + t] = inta[t];
        stab[64 + t] = params[t];
        int c = d_cnt[atom * PBLK + t];           // 32 consecutive ints
        scnt[t] = c;
        int x = c;
#pragma unroll
        for (int dd = 1; dd < 32; dd <<= 1) {
            int y = __shfl_up_sync(0xffffffffu, x, dd);
            if (lane >= dd) x += y;
        }
        soff[t] = x - c;
        if (t == 31) stot = x;
    }
    __syncthreads();

    const int n = stot;

    // parallel pass: 4 lanes per cell cover slots 0..3 of all 32 cells
    {
        const int r = (t >> 2);                   // cell 0..31
        const int s = (t & 3);                    // slot 0..3
        if (s < scnt[r])
            recs[soff[r] + s] = src[r * SLOT + s];
    }
    // remainder: slots 4..c-1 (rare), one lane per cell
    if (t < 32) {
        const int c = scnt[t];
        for (int s = 4; s < c; ++s)
            recs[soff[t] + s] = src[t * SLOT + s];
    }
    __syncthreads();

    // Phase A: per-pair distance + cutoff
    const float icp = 3.14159265358979323846f / cutoff[0];
    for (int p = t; p < n; p += 128) {
        float4 v = recs[p];
        float d  = sqrtf(v.x*v.x + v.y*v.y + v.z*v.z);
        float c  = 0.5f * __cosf(d * icp) + 0.5f;
        dfc[p]   = make_float2(d, c * c);
    }
    __syncthreads();

    // Phase B: thread = (w = t&7, slice = t>>3)
    const int w  = t & 7;
    const int sl = t >> 3;

    float acc[NL];
#pragma unroll
    for (int l = 0; l < NL; ++l) acc[l] = 0.f;

    for (int p = sl; p < n; p += 16) {
        float4 v  = recs[p];
        float2 df = dfc[p];
        int   sp  = __float_as_int(v.w);
        float tt  = df.x - stab[sp*8 + w];
        float r   = stab[64 + sp*8 + w] * __expf(stab[32 + sp*8 + w] * tt * tt);
        float q   = df.y * r;
        float qx = q * v.x, qy = q * v.y, qz = q * v.z;
        acc[0]  += q;
        acc[1]  += qx;        acc[2]  += qy;        acc[3]  += qz;
        acc[4]  += qx * v.x;  acc[5]  += qx * v.y;  acc[6]  += qx * v.z;
        acc[7]  += qy * v.x;  acc[8]  += qy * v.y;  acc[9]  += qy * v.z;
        acc[10] += qz * v.x;  acc[11] += qz * v.y;  acc[12] += qz * v.z;
    }

#pragma unroll
    for (int l = 0; l < NL; ++l) {
        acc[l] += __shfl_xor_sync(0xffffffffu, acc[l], 8);
        acc[l] += __shfl_xor_sync(0xffffffffu, acc[l], 16);
    }
    if (lane < 8) {
#pragma unroll
        for (int l = 0; l < NL; ++l)
            red[(l * NWAVE + lane) * 4 + warp] = acc[l];
    }
    __syncthreads();

    if (t < NFEAT) {
        float4 v = *reinterpret_cast<const float4*>(&red[t * 4]);
        swout[(size_t)atom * NFEAT + t] = (v.x + v.y) + (v.z + v.w);
    }
}

// ---------------------------------------------------------------------------
// Kernel 2b: density[atom][m] = sum_l ( sum_w sw[l][w]*hp[l][w][m] )^2
// ---------------------------------------------------------------------------
__global__ void __launch_bounds__(128)
k_stage2(const float* __restrict__ hyper,      // (3, 8, 128)
         const int*   __restrict__ index_para, // (13,)
         const float* __restrict__ sw,         // (8192, 104)
         float*       __restrict__ out)        // (8192, 128)
{
    const int t = threadIdx.x;

    float hp[NFEAT];
#pragma unroll
    for (int l = 0; l < NL; ++l) {
        int ip = index_para[l];
#pragma unroll
        for (int w = 0; w < NWAVE; ++w)
            hp[l*NWAVE + w] = hyper[(ip*NWAVE + w)*NORBIT + t];
    }

    __shared__ float swsm[GATOMS * NFEAT];
    const int base = blockIdx.x * GATOMS;

    for (int i = t; i < GATOMS * NFEAT; i += 128)
        swsm[i] = sw[(size_t)base * NFEAT + i];
    __syncthreads();

#pragma unroll 2
    for (int g = 0; g < GATOMS; ++g) {
        const float4* s4 = reinterpret_cast<const float4*>(&swsm[g * NFEAT]);
        float dens = 0.f;
#pragma unroll
        for (int l = 0; l < NL; ++l) {
            float4 a = s4[l*2], bb = s4[l*2+1];
            float h = a.x*hp[l*8+0] + a.y*hp[l*8+1] + a.z*hp[l*8+2] + a.w*hp[l*8+3]
                    + bb.x*hp[l*8+4] + bb.y*hp[l*8+5] + bb.z*hp[l*8+6] + bb.w*hp[l*8+7];
            dens += h * h;
        }
        out[(size_t)(base + g)*NORBIT + t] = dens;
    }
}

// ---------------------------------------------------------------------------
extern "C" void kernel_launch(void* const* d_in, const int* in_sizes, int n_in,
                              void* d_out, int out_size)
{
    const float* cart    = (const float*)d_in[0];
    const int*   species = (const int*)  d_in[2];
    const int*   aidx    = (const int*)  d_in[3];
    const float* shifts  = (const float*)d_in[4];
    const float* rs      = (const float*)d_in[5];
    const float* inta    = (const float*)d_in[6];
    const float* params  = (const float*)d_in[7];
    const float* hyper   = (const float*)d_in[8];
    const int*   ipara   = (const int*)  d_in[9];
    const float* cutoff  = (const float*)d_in[10];
    float*       out     = (float*)d_out;

    void* swp = nullptr;
    cudaGetSymbolAddress(&swp, d_sw);

    dim3 pgrid(PBLK, NBATCH);
    k_pairs<<<pgrid, 256>>>(cart, species, aidx, shifts);
    k_accum<<<TOTATOM, 128>>>(rs, inta, params, cutoff, (float*)swp);
    k_stage2<<<TOTATOM / GATOMS, 128>>>(hyper, ipara, (const float*)swp, out);
}